// round 13
// baseline (speedup 1.0000x reference)
#include <cuda_runtime.h>
#include <cuda_bf16.h>
#include <cuda_fp16.h>
#include <cstdint>
#include <math.h>

#define BATCH 4
#define HEADS 16
#define SEQ   1024
#define HD    64
#define DIM   1024
#define ATT_SCALE 0.125f   // HD^-0.5

// ---------------------------------------------------------------------------
// Device-global scratch (allocation-free per harness rules)
// ---------------------------------------------------------------------------
__device__ __align__(16) __nv_bfloat16 g_qh[BATCH*HEADS*SEQ*HD], g_ql[BATCH*HEADS*SEQ*HD];
__device__ __align__(16) __nv_bfloat16 g_kh[BATCH*HEADS*SEQ*HD], g_kl[BATCH*HEADS*SEQ*HD];
__device__ __align__(16) __nv_bfloat16 g_vh[BATCH*HEADS*SEQ*HD], g_vl[BATCH*HEADS*SEQ*HD];

__device__ __align__(16) __half g_x_hi[BATCH*SEQ*DIM],  g_x_lo[BATCH*SEQ*DIM];
__device__ __align__(16) __half g_ah_hi[BATCH*SEQ*DIM], g_ah_lo[BATCH*SEQ*DIM];
__device__ __align__(16) __half g_wq[3*DIM*DIM];   // [N=3072][K=1024], fp16
__device__ __align__(16) __half g_wp[DIM*DIM];     // [N=1024][K=1024], fp16

// ---------------------------------------------------------------------------
// PTX helpers legal on plain compute_103 (sm_80-era instructions)
// ---------------------------------------------------------------------------
__device__ __forceinline__ uint32_t smem_u32(const void* p) {
    uint32_t a;
    asm("{ .reg .u64 t; cvta.to.shared.u64 t, %1; cvt.u32.u64 %0, t; }" : "=r"(a) : "l"(p));
    return a;
}
__device__ __forceinline__ void cpasync16(uint32_t dst, const void* src) {
    asm volatile("cp.async.cg.shared.global [%0], [%1], 16;" :: "r"(dst), "l"(src));
}
__device__ __forceinline__ void ldsm4(uint32_t* r, uint32_t addr) {
    asm volatile("ldmatrix.sync.aligned.m8n8.x4.shared.b16 {%0,%1,%2,%3}, [%4];"
        : "=r"(r[0]), "=r"(r[1]), "=r"(r[2]), "=r"(r[3]) : "r"(addr));
}
__device__ __forceinline__ void ldsm4t(uint32_t* r, uint32_t addr) {
    asm volatile("ldmatrix.sync.aligned.m8n8.x4.trans.shared.b16 {%0,%1,%2,%3}, [%4];"
        : "=r"(r[0]), "=r"(r[1]), "=r"(r[2]), "=r"(r[3]) : "r"(addr));
}
// bf16 MMA (attention)
__device__ __forceinline__ void mma16816(float* c, const uint32_t* a, const uint32_t* b) {
    asm volatile(
        "mma.sync.aligned.m16n8k16.row.col.f32.bf16.bf16.f32 "
        "{%0,%1,%2,%3}, {%4,%5,%6,%7}, {%8,%9}, {%0,%1,%2,%3};"
        : "+f"(c[0]), "+f"(c[1]), "+f"(c[2]), "+f"(c[3])
        : "r"(a[0]), "r"(a[1]), "r"(a[2]), "r"(a[3]), "r"(b[0]), "r"(b[1]));
}
// fp16 MMA (GEMMs)
__device__ __forceinline__ void mma16816h(float* c, const uint32_t* a, const uint32_t* b) {
    asm volatile(
        "mma.sync.aligned.m16n8k16.row.col.f32.f16.f16.f32 "
        "{%0,%1,%2,%3}, {%4,%5,%6,%7}, {%8,%9}, {%0,%1,%2,%3};"
        : "+f"(c[0]), "+f"(c[1]), "+f"(c[2]), "+f"(c[3])
        : "r"(a[0]), "r"(a[1]), "r"(a[2]), "r"(a[3]), "r"(b[0]), "r"(b[1]));
}
// bf16 hi/lo pack
__device__ __forceinline__ void split2(float x, float y, uint32_t& hi, uint32_t& lo) {
    __nv_bfloat16 hx = __float2bfloat16_rn(x), hy = __float2bfloat16_rn(y);
    __nv_bfloat16 lx = __float2bfloat16_rn(x - __bfloat162float(hx));
    __nv_bfloat16 ly = __float2bfloat16_rn(y - __bfloat162float(hy));
    __nv_bfloat162 H(hx, hy), L(lx, ly);
    hi = *reinterpret_cast<uint32_t*>(&H);
    lo = *reinterpret_cast<uint32_t*>(&L);
}
// fp16 hi/lo pack
__device__ __forceinline__ void split2h(float x, float y, uint32_t& hi, uint32_t& lo) {
    __half hx = __float2half_rn(x), hy = __float2half_rn(y);
    __half lx = __float2half_rn(x - __half2float(hx));
    __half ly = __float2half_rn(y - __half2float(hy));
    __half2 H = __halves2half2(hx, hy), L = __halves2half2(lx, ly);
    hi = *reinterpret_cast<uint32_t*>(&H);
    lo = *reinterpret_cast<uint32_t*>(&L);
}

// ---------------------------------------------------------------------------
// Prep kernels
// ---------------------------------------------------------------------------
__global__ void split_x(const float* __restrict__ src, int n4)
{
    int i = blockIdx.x * blockDim.x + threadIdx.x;
    if (i >= n4) return;
    float4 v = reinterpret_cast<const float4*>(src)[i];
    uint32_t h0, l0, h1, l1;
    split2h(v.x, v.y, h0, l0);
    split2h(v.z, v.w, h1, l1);
    uint32_t* ph = reinterpret_cast<uint32_t*>(g_x_hi) + i*2;
    uint32_t* pl = reinterpret_cast<uint32_t*>(g_x_lo) + i*2;
    ph[0] = h0; ph[1] = h1; pl[0] = l0; pl[1] = l1;
}

template<int W>     // 0: w_qkv [1024][3072], 1: w_proj [1024][1024]
__global__ void transpose_w(const float* __restrict__ src)
{
    constexpr int R = DIM;
    constexpr int C = (W == 0) ? 3*DIM : DIM;
    __half* dh = (W == 0) ? g_wq : g_wp;
    __shared__ float tile[32][33];
    const int c0 = blockIdx.x * 32, r0 = blockIdx.y * 32;
    const int x = threadIdx.x, y = threadIdx.y;  // 32 x 8
    #pragma unroll
    for (int i = 0; i < 32; i += 8)
        tile[y + i][x] = src[(size_t)(r0 + y + i) * C + c0 + x];
    __syncthreads();
    #pragma unroll
    for (int i = 0; i < 32; i += 8) {
        float v = tile[x][y + i];
        dh[(size_t)(c0 + y + i) * R + r0 + x] = __float2half_rn(v);
    }
}

// ---------------------------------------------------------------------------
// fp16 2-term GEMM: C = (Ah+Al) @ B^T + bias, B fp16 (weights rounded).
// R6 schedule: 256 thr, 8 warps, 32x64 warp tiles, BK=32, 80B stride,
// double-buffered cp.async, 2 passes (AhB then AlB), distinct accumulators.
// MODE 1: QKV epilogue -> bf16 hi/lo Q/K/V.  MODE 2: plain fp32 (proj).
// ---------------------------------------------------------------------------
#define T_STR    40
#define TILE_B   (128*T_STR*2)           // 10240 B per 128x32 tile
#define OFF_AH   0
#define OFF_AL   (TILE_B)
#define OFF_B    (2*TILE_B)
#define STAGE_B  (3*TILE_B)              // 30720 B
#define NSTAGE   (DIM/32)

template<int MODE>
__global__ __launch_bounds__(256, 2)
void mma_gemm(const float* __restrict__ bias, float* __restrict__ Cout, int N)
{
    constexpr int K = 1024;
    extern __shared__ char smem[];
    const uint32_t sb = smem_u32(smem);

    const int t = threadIdx.x, wid = t >> 5, lane = t & 31;
    const int wr = wid & 3, wc = wid >> 2;
    const int lp = lane & 15, lq = lane >> 4;
    const int m0 = blockIdx.y * 128, n0 = blockIdx.x * 128;

    const __half* Ah = (MODE == 1) ? g_x_hi : g_ah_hi;
    const __half* Al = (MODE == 1) ? g_x_lo : g_ah_lo;
    const __half* Bw = (MODE == 1) ? g_wq : g_wp;

    const __half* aH = Ah + (size_t)m0 * K;
    const __half* aL = Al + (size_t)m0 * K;
    const __half* bW = Bw + (size_t)n0 * K;

    const uint32_t arow = (uint32_t)((wr*32 + lp) * 80 + lq * 16);
    const uint32_t brow = (uint32_t)((wc*64 + lp) * 80 + lq * 16);

    float acc[2][8][4];
    #pragma unroll
    for (int i = 0; i < 2; i++)
        #pragma unroll
        for (int j = 0; j < 8; j++)
            #pragma unroll
            for (int q = 0; q < 4; q++) acc[i][j][q] = 0.f;

    auto load_stage = [&](int buf, int ks) {
        const uint32_t st = sb + buf * STAGE_B;
        const int k0h = ks * 32;
        #pragma unroll
        for (int rep = 0; rep < 2; rep++) {
            const int idx = t + rep * 256;
            const int r = idx >> 2, s = idx & 3;
            const uint32_t so = (uint32_t)(r * 80 + s * 16);
            const size_t go = (size_t)r * K + k0h + s * 8;
            cpasync16(st + OFF_AH + so, aH + go);
            cpasync16(st + OFF_AL + so, aL + go);
            cpasync16(st + OFF_B  + so, bW + go);
        }
        asm volatile("cp.async.commit_group;" ::: "memory");
    };

    load_stage(0, 0);

    for (int ks = 0; ks < NSTAGE; ks++) {
        if (ks + 1 < NSTAGE) {
            load_stage((ks + 1) & 1, ks + 1);
            asm volatile("cp.async.wait_group 1;" ::: "memory");
        } else {
            asm volatile("cp.async.wait_group 0;" ::: "memory");
        }
        __syncthreads();

        const uint32_t st = sb + (ks & 1) * STAGE_B;
        #pragma unroll
        for (int kk = 0; kk < 2; kk++) {
            const uint32_t kb = kk * 32;
            uint32_t bf[4][4];
            #pragma unroll
            for (int ng = 0; ng < 4; ng++)
                ldsm4(bf[ng], st + OFF_B + brow + ng*1280 + kb);
            uint32_t ahf[2][4], alf[2][4];
            #pragma unroll
            for (int rg = 0; rg < 2; rg++) {
                ldsm4(ahf[rg], st + OFF_AH + arow + rg*1280 + kb);
                ldsm4(alf[rg], st + OFF_AL + arow + rg*1280 + kb);
            }

            // Pass 1: Ah x B   (16 MMAs, all-distinct accumulators)
            #pragma unroll
            for (int rg = 0; rg < 2; rg++)
                #pragma unroll
                for (int ng = 0; ng < 4; ng++) {
                    uint32_t b0[2] = {bf[ng][0], bf[ng][2]};
                    uint32_t b1[2] = {bf[ng][1], bf[ng][3]};
                    mma16816h(acc[rg][2*ng],   ahf[rg], b0);
                    mma16816h(acc[rg][2*ng+1], ahf[rg], b1);
                }
            // Pass 2: Al x B
            #pragma unroll
            for (int rg = 0; rg < 2; rg++)
                #pragma unroll
                for (int ng = 0; ng < 4; ng++) {
                    uint32_t b0[2] = {bf[ng][0], bf[ng][2]};
                    uint32_t b1[2] = {bf[ng][1], bf[ng][3]};
                    mma16816h(acc[rg][2*ng],   alf[rg], b0);
                    mma16816h(acc[rg][2*ng+1], alf[rg], b1);
                }
        }
        __syncthreads();
    }

    // ---- Epilogue ----
    const int gcb = n0 + wc*64;       // 64-aligned -> single head / single q|k|v
    const int lrow = lane >> 2, lc2 = 2*(lane & 3);

    if (MODE == 1) {
        const int three = gcb >> 10;
        const int h     = (gcb >> 6) & (HEADS - 1);
        __nv_bfloat16* dsth = (three == 0) ? g_qh : (three == 1) ? g_kh : g_vh;
        __nv_bfloat16* dstl = (three == 0) ? g_ql : (three == 1) ? g_kl : g_vl;
        const float sc = (three == 0) ? ATT_SCALE : 1.0f;
        #pragma unroll
        for (int rg = 0; rg < 2; rg++) {
            const int row = m0 + wr*32 + rg*16 + lrow;
            const int b = row >> 10, n = row & (SEQ - 1);
            const size_t r0i = (((size_t)(b*HEADS + h))*SEQ + n)*HD;
            const size_t r1i = r0i + (size_t)8*HD;
            #pragma unroll
            for (int ng = 0; ng < 4; ng++)
                #pragma unroll
                for (int j = 0; j < 2; j++) {
                    const int col = gcb + ng*16 + j*8 + lc2;
                    const int dd = col & 63;
                    const float b0 = bias[col], b1 = bias[col + 1];
                    float* c = acc[rg][2*ng + j];
                    uint32_t h01, l01, h23, l23;
                    split2((c[0] + b0) * sc, (c[1] + b1) * sc, h01, l01);
                    split2((c[2] + b0) * sc, (c[3] + b1) * sc, h23, l23);
                    *reinterpret_cast<uint32_t*>(dsth + r0i + dd) = h01;
                    *reinterpret_cast<uint32_t*>(dstl + r0i + dd) = l01;
                    *reinterpret_cast<uint32_t*>(dsth + r1i + dd) = h23;
                    *reinterpret_cast<uint32_t*>(dstl + r1i + dd) = l23;
                }
        }
    } else {
        #pragma unroll
        for (int rg = 0; rg < 2; rg++) {
            const int row = m0 + wr*32 + rg*16 + lrow;
            float* dst0 = Cout + (size_t)row * N;
            float* dst1 = Cout + (size_t)(row + 8) * N;
            #pragma unroll
            for (int ng = 0; ng < 4; ng++)
                #pragma unroll
                for (int j = 0; j < 2; j++) {
                    const int col = gcb + ng*16 + j*8 + lc2;
                    const float b0 = bias[col], b1 = bias[col + 1];
                    float* c = acc[rg][2*ng + j];
                    *reinterpret_cast<float2*>(dst0 + col) = make_float2(c[0] + b0, c[1] + b1);
                    *reinterpret_cast<float2*>(dst1 + col) = make_float2(c[2] + b0, c[3] + b1);
                }
        }
    }
}

// ---------------------------------------------------------------------------
// Flash attention (R11, bf16 3-term, unchanged except fp16 epilogue output).
// Grid (SEQ/128, B*H), 256 thr (8 warps x m16 rows). Bc=64 keys/iter.
// ---------------------------------------------------------------------------
#define AT_T     72                        // halves per smem row (144 B)
#define AT_QH    0
#define AT_QL    18432
#define AT_STG   36864                     // first KV stage
#define AT_STGB  36864                     // stage size
#define AT_KL    9216
#define AT_VH    18432
#define AT_VL    27648
#define AT_SMEM  (AT_STG + 2*AT_STGB)      // 110592 B

__global__ __launch_bounds__(256, 2)
void attn_mma()
{
    extern __shared__ char smem[];
    const uint32_t sb = smem_u32(smem);
    const int t = threadIdx.x, lane = t & 31, wid = t >> 5;
    const int bh = blockIdx.y;
    const int r0 = blockIdx.x * 128;
    const size_t bho = (size_t)bh * SEQ * HD;

    const __nv_bfloat16* Qh = g_qh + bho + (size_t)r0 * HD;
    const __nv_bfloat16* Ql = g_ql + bho + (size_t)r0 * HD;
    const __nv_bfloat16* Kh = g_kh + bho;
    const __nv_bfloat16* Kl = g_kl + bho;
    const __nv_bfloat16* Vh = g_vh + bho;
    const __nv_bfloat16* Vl = g_vl + bho;

    // Q tiles (once): 128 rows x 8 segs x {hi,lo} = 2048 cp.async transfers
    for (int i = t; i < 2048; i += 256) {
        const int tile = i >> 10, rem = i & 1023, row = rem >> 3, seg = rem & 7;
        const __nv_bfloat16* src = (tile ? Ql : Qh) + (size_t)row * HD + seg * 8;
        cpasync16(sb + (tile ? AT_QL : AT_QH) + row*144 + seg*16, src);
    }
    auto load_stage = [&](int buf, int j0) {
        const uint32_t st = sb + AT_STG + buf * AT_STGB;
        for (int i = t; i < 2048; i += 256) {
            const int tile = i >> 9, rem = i & 511, row = rem >> 3, seg = rem & 7;
            const __nv_bfloat16* src =
                (tile == 0 ? Kh : tile == 1 ? Kl : tile == 2 ? Vh : Vl)
                + (size_t)(j0 + row) * HD + seg * 8;
            cpasync16(st + tile*9216 + row*144 + seg*16, src);
        }
        asm volatile("cp.async.commit_group;" ::: "memory");
    };
    load_stage(0, 0);   // commits Q too

    // ldmatrix per-thread offsets (bytes)
    const int mrow = lane & 7, mid = lane >> 3;
    const uint32_t qoff = (uint32_t)(((wid*16 + ((mid & 1) ? 8 : 0) + mrow) * AT_T
                                      + ((mid & 2) ? 8 : 0)) * 2);
    const uint32_t koff = (uint32_t)(((((mid & 2) ? 8 : 0) + mrow) * AT_T
                                      + ((mid & 1) ? 8 : 0)) * 2);
    const uint32_t voff = (uint32_t)(((((mid & 1) ? 8 : 0) + mrow) * AT_T
                                      + ((mid & 2) ? 8 : 0)) * 2);

    float o[8][4];
    #pragma unroll
    for (int i = 0; i < 8; i++)
        #pragma unroll
        for (int q = 0; q < 4; q++) o[i][q] = 0.f;
    float mA = -1e30f, mB = -1e30f, lA = 0.f, lB = 0.f;

    for (int it = 0; it < SEQ/64; it++) {
        if (it + 1 < SEQ/64) {
            load_stage((it + 1) & 1, (it + 1) * 64);
            asm volatile("cp.async.wait_group 1;" ::: "memory");
        } else {
            asm volatile("cp.async.wait_group 0;" ::: "memory");
        }
        __syncthreads();

        const uint32_t KHb = sb + AT_STG + (it & 1) * AT_STGB;
        const uint32_t KLb = KHb + AT_KL, VHb = KHb + AT_VH, VLb = KHb + AT_VL;

        // ---- S = Q K^T (split), chains interleaved across s[2j]/s[2j+1] ----
        float s[8][4];
        #pragma unroll
        for (int i = 0; i < 8; i++)
            #pragma unroll
            for (int q = 0; q < 4; q++) s[i][q] = 0.f;

        #pragma unroll
        for (int g = 0; g < 4; g++) {
            uint32_t qfh[4], qfl[4];
            ldsm4(qfh, sb + AT_QH + qoff + g*32);
            ldsm4(qfl, sb + AT_QL + qoff + g*32);
            #pragma unroll
            for (int j = 0; j < 4; j++) {
                uint32_t kh[4], kl[4];
                const uint32_t off = koff + (uint32_t)((j*16*AT_T + g*16) * 2);
                ldsm4(kh, KHb + off);
                ldsm4(kl, KLb + off);
                uint32_t b0h[2] = {kh[0], kh[1]}, b1h[2] = {kh[2], kh[3]};
                uint32_t b0l[2] = {kl[0], kl[1]}, b1l[2] = {kl[2], kl[3]};
                mma16816(s[2*j],   qfh, b0h);
                mma16816(s[2*j+1], qfh, b1h);
                mma16816(s[2*j],   qfl, b0h);
                mma16816(s[2*j+1], qfl, b1h);
                mma16816(s[2*j],   qfh, b0l);
                mma16816(s[2*j+1], qfh, b1l);
            }
        }

        // ---- online softmax (rows: A = lane/4, B = lane/4 + 8) ----
        float mxA = s[0][0], mxB = s[0][2];
        #pragma unroll
        for (int i = 0; i < 8; i++) {
            mxA = fmaxf(mxA, fmaxf(s[i][0], s[i][1]));
            mxB = fmaxf(mxB, fmaxf(s[i][2], s[i][3]));
        }
        mxA = fmaxf(mxA, __shfl_xor_sync(0xffffffffu, mxA, 1));
        mxA = fmaxf(mxA, __shfl_xor_sync(0xffffffffu, mxA, 2));
        mxB = fmaxf(mxB, __shfl_xor_sync(0xffffffffu, mxB, 1));
        mxB = fmaxf(mxB, __shfl_xor_sync(0xffffffffu, mxB, 2));
        const float nmA = fmaxf(mA, mxA), nmB = fmaxf(mB, mxB);

        float ltA = 0.f, ltB = 0.f;
        #pragma unroll
        for (int i = 0; i < 8; i++) {
            s[i][0] = __expf(s[i][0] - nmA); ltA += s[i][0];
            s[i][1] = __expf(s[i][1] - nmA); ltA += s[i][1];
            s[i][2] = __expf(s[i][2] - nmB); ltB += s[i][2];
            s[i][3] = __expf(s[i][3] - nmB); ltB += s[i][3];
        }
        ltA += __shfl_xor_sync(0xffffffffu, ltA, 1);
        ltA += __shfl_xor_sync(0xffffffffu, ltA, 2);
        ltB += __shfl_xor_sync(0xffffffffu, ltB, 1);
        ltB += __shfl_xor_sync(0xffffffffu, ltB, 2);

        const float aA = __expf(mA - nmA), aB = __expf(mB - nmB);
        lA = lA * aA + ltA;  mA = nmA;
        lB = lB * aB + ltB;  mB = nmB;
        #pragma unroll
        for (int i = 0; i < 8; i++) {
            o[i][0] *= aA; o[i][1] *= aA;
            o[i][2] *= aB; o[i][3] *= aB;
        }

        // ---- O += P V (split), chains interleaved across o[2j]/o[2j+1] ----
        #pragma unroll
        for (int g = 0; g < 4; g++) {
            uint32_t ph[4], pl[4];
            split2(s[2*g][0],   s[2*g][1],   ph[0], pl[0]);
            split2(s[2*g][2],   s[2*g][3],   ph[1], pl[1]);
            split2(s[2*g+1][0], s[2*g+1][1], ph[2], pl[2]);
            split2(s[2*g+1][2], s[2*g+1][3], ph[3], pl[3]);
            #pragma unroll
            for (int j = 0; j < 4; j++) {
                uint32_t vh[4], vl[4];
                const uint32_t off = voff + (uint32_t)((g*16*AT_T + j*16) * 2);
                ldsm4t(vh, VHb + off);
                ldsm4t(vl, VLb + off);
                uint32_t b0h[2] = {vh[0], vh[1]}, b1h[2] = {vh[2], vh[3]};
                uint32_t b0l[2] = {vl[0], vl[1]}, b1l[2] = {vl[2], vl[3]};
                mma16816(o[2*j],   ph, b0h);
                mma16816(o[2*j+1], ph, b1h);
                mma16816(o[2*j],   pl, b0h);
                mma16816(o[2*j+1], pl, b1h);
                mma16816(o[2*j],   ph, b0l);
                mma16816(o[2*j+1], ph, b1l);
            }
        }
        __syncthreads();
    }

    // ---- epilogue: write fp16 hi/lo attention output (for fp16 proj GEMM) ----
    const float iA = 1.f / lA, iB = 1.f / lB;
    const int b = bh >> 4, h = bh & 15;
    const int nA = r0 + wid*16 + (lane >> 2), nB = nA + 8;
    const size_t baseA = ((size_t)(b*SEQ + nA))*DIM + h*HD;
    const size_t baseB = ((size_t)(b*SEQ + nB))*DIM + h*HD;
    #pragma unroll
    for (int tt = 0; tt < 8; tt++) {
        const int d = tt*8 + 2*(lane & 3);
        uint32_t hA, lAo, hB, lBo;
        split2h(o[tt][0]*iA, o[tt][1]*iA, hA, lAo);
        split2h(o[tt][2]*iB, o[tt][3]*iB, hB, lBo);
        *reinterpret_cast<uint32_t*>(g_ah_hi + baseA + d) = hA;
        *reinterpret_cast<uint32_t*>(g_ah_lo + baseA + d) = lAo;
        *reinterpret_cast<uint32_t*>(g_ah_hi + baseB + d) = hB;
        *reinterpret_cast<uint32_t*>(g_ah_lo + baseB + d) = lBo;
    }
}

// ---------------------------------------------------------------------------
extern "C" void kernel_launch(void* const* d_in, const int* in_sizes, int n_in,
                              void* d_out, int out_size)
{
    const float* x      = (const float*)d_in[0];
    const float* w_qkv  = (const float*)d_in[1];
    const float* b_qkv  = (const float*)d_in[2];
    const float* w_proj = (const float*)d_in[3];
    const float* b_proj = (const float*)d_in[4];
    float* out = (float*)d_out;

    const int gemm_smem = 2 * STAGE_B;   // 61440 B
    cudaFuncSetAttribute(mma_gemm<1>, cudaFuncAttributeMaxDynamicSharedMemorySize, gemm_smem);
    cudaFuncSetAttribute(mma_gemm<2>, cudaFuncAttributeMaxDynamicSharedMemorySize, gemm_smem);
    cudaFuncSetAttribute(attn_mma,    cudaFuncAttributeMaxDynamicSharedMemorySize, AT_SMEM);

    // 0) Prep: split x (fp16 hi/lo), transpose weights (fp16)
    split_x<<<4096, 256>>>(x, BATCH*SEQ*DIM/4);
    transpose_w<0><<<dim3(96, 32), dim3(32, 8)>>>(w_qkv);
    transpose_w<1><<<dim3(32, 32), dim3(32, 8)>>>(w_proj);

    // 1) QKV GEMM (fp16 2-term) -> bf16 hi/lo Q/K/V (Q pre-scaled)
    mma_gemm<1><<<dim3(3*DIM/128, BATCH*SEQ/128), 256, gemm_smem>>>(b_qkv, nullptr, 3*DIM);

    // 2) Flash attention (bf16 3-term HMMA) -> fp16 hi/lo g_ah
    attn_mma<<<dim3(SEQ/128, BATCH*HEADS), 256, AT_SMEM>>>();

    // 3) Projection GEMM (fp16 2-term)
    mma_gemm<2><<<dim3(DIM/128, BATCH*SEQ/128), 256, gemm_smem>>>(b_proj, out, DIM);
}

// round 14
// speedup vs baseline: 1.1075x; 1.1075x over previous
#include <cuda_runtime.h>
#include <cuda_bf16.h>
#include <cuda_fp16.h>
#include <cstdint>
#include <math.h>

#define BATCH 4
#define HEADS 16
#define SEQ   1024
#define HD    64
#define DIM   1024
#define ATT_SCALE 0.125f   // HD^-0.5

// ---------------------------------------------------------------------------
// Device-global scratch (allocation-free per harness rules)
// ---------------------------------------------------------------------------
__device__ __align__(16) __half g_qh[BATCH*HEADS*SEQ*HD], g_ql[BATCH*HEADS*SEQ*HD];
__device__ __align__(16) __half g_k[BATCH*HEADS*SEQ*HD];   // single fp16
__device__ __align__(16) __half g_v[BATCH*HEADS*SEQ*HD];   // single fp16

__device__ __align__(16) __half g_x_hi[BATCH*SEQ*DIM],  g_x_lo[BATCH*SEQ*DIM];
__device__ __align__(16) __half g_ah_hi[BATCH*SEQ*DIM], g_ah_lo[BATCH*SEQ*DIM];
__device__ __align__(16) __half g_wq[3*DIM*DIM];   // [N=3072][K=1024], fp16
__device__ __align__(16) __half g_wp[DIM*DIM];     // [N=1024][K=1024], fp16

// ---------------------------------------------------------------------------
// PTX helpers legal on plain compute_103 (sm_80-era instructions)
// ---------------------------------------------------------------------------
__device__ __forceinline__ uint32_t smem_u32(const void* p) {
    uint32_t a;
    asm("{ .reg .u64 t; cvta.to.shared.u64 t, %1; cvt.u32.u64 %0, t; }" : "=r"(a) : "l"(p));
    return a;
}
__device__ __forceinline__ void cpasync16(uint32_t dst, const void* src) {
    asm volatile("cp.async.cg.shared.global [%0], [%1], 16;" :: "r"(dst), "l"(src));
}
__device__ __forceinline__ void ldsm4(uint32_t* r, uint32_t addr) {
    asm volatile("ldmatrix.sync.aligned.m8n8.x4.shared.b16 {%0,%1,%2,%3}, [%4];"
        : "=r"(r[0]), "=r"(r[1]), "=r"(r[2]), "=r"(r[3]) : "r"(addr));
}
__device__ __forceinline__ void ldsm4t(uint32_t* r, uint32_t addr) {
    asm volatile("ldmatrix.sync.aligned.m8n8.x4.trans.shared.b16 {%0,%1,%2,%3}, [%4];"
        : "=r"(r[0]), "=r"(r[1]), "=r"(r[2]), "=r"(r[3]) : "r"(addr));
}
// fp16 MMA
__device__ __forceinline__ void mma16816h(float* c, const uint32_t* a, const uint32_t* b) {
    asm volatile(
        "mma.sync.aligned.m16n8k16.row.col.f32.f16.f16.f32 "
        "{%0,%1,%2,%3}, {%4,%5,%6,%7}, {%8,%9}, {%0,%1,%2,%3};"
        : "+f"(c[0]), "+f"(c[1]), "+f"(c[2]), "+f"(c[3])
        : "r"(a[0]), "r"(a[1]), "r"(a[2]), "r"(a[3]), "r"(b[0]), "r"(b[1]));
}
// fp16 hi/lo pack
__device__ __forceinline__ void split2h(float x, float y, uint32_t& hi, uint32_t& lo) {
    __half hx = __float2half_rn(x), hy = __float2half_rn(y);
    __half lx = __float2half_rn(x - __half2float(hx));
    __half ly = __float2half_rn(y - __half2float(hy));
    __half2 H = __halves2half2(hx, hy), L = __halves2half2(lx, ly);
    hi = *reinterpret_cast<uint32_t*>(&H);
    lo = *reinterpret_cast<uint32_t*>(&L);
}
__device__ __forceinline__ uint32_t pack2h(float x, float y) {
    __half2 H = __halves2half2(__float2half_rn(x), __float2half_rn(y));
    return *reinterpret_cast<uint32_t*>(&H);
}

// ---------------------------------------------------------------------------
// Prep kernels
// ---------------------------------------------------------------------------
__global__ void split_x(const float* __restrict__ src, int n4)
{
    int i = blockIdx.x * blockDim.x + threadIdx.x;
    if (i >= n4) return;
    float4 v = reinterpret_cast<const float4*>(src)[i];
    uint32_t h0, l0, h1, l1;
    split2h(v.x, v.y, h0, l0);
    split2h(v.z, v.w, h1, l1);
    uint32_t* ph = reinterpret_cast<uint32_t*>(g_x_hi) + i*2;
    uint32_t* pl = reinterpret_cast<uint32_t*>(g_x_lo) + i*2;
    ph[0] = h0; ph[1] = h1; pl[0] = l0; pl[1] = l1;
}

template<int W>     // 0: w_qkv [1024][3072], 1: w_proj [1024][1024]
__global__ void transpose_w(const float* __restrict__ src)
{
    constexpr int R = DIM;
    constexpr int C = (W == 0) ? 3*DIM : DIM;
    __half* dh = (W == 0) ? g_wq : g_wp;
    __shared__ float tile[32][33];
    const int c0 = blockIdx.x * 32, r0 = blockIdx.y * 32;
    const int x = threadIdx.x, y = threadIdx.y;  // 32 x 8
    #pragma unroll
    for (int i = 0; i < 32; i += 8)
        tile[y + i][x] = src[(size_t)(r0 + y + i) * C + c0 + x];
    __syncthreads();
    #pragma unroll
    for (int i = 0; i < 32; i += 8) {
        float v = tile[x][y + i];
        dh[(size_t)(c0 + y + i) * R + r0 + x] = __float2half_rn(v);
    }
}

// ---------------------------------------------------------------------------
// fp16 2-term GEMM: C = (Ah+Al) @ B^T + bias, B fp16 (weights rounded).
// 256 thr, 8 warps, 32x64 warp tiles, BK=32, 80B stride, double-buffered.
// MODE 1: QKV epilogue -> Q fp16 hi/lo (pre-scaled), K/V single fp16.
// MODE 2: plain fp32 epilogue (proj).
// ---------------------------------------------------------------------------
#define T_STR    40
#define TILE_B   (128*T_STR*2)           // 10240 B per 128x32 tile
#define OFF_AH   0
#define OFF_AL   (TILE_B)
#define OFF_B    (2*TILE_B)
#define STAGE_B  (3*TILE_B)              // 30720 B
#define NSTAGE   (DIM/32)

template<int MODE>
__global__ __launch_bounds__(256, 2)
void mma_gemm(const float* __restrict__ bias, float* __restrict__ Cout, int N)
{
    constexpr int K = 1024;
    extern __shared__ char smem[];
    const uint32_t sb = smem_u32(smem);

    const int t = threadIdx.x, wid = t >> 5, lane = t & 31;
    const int wr = wid & 3, wc = wid >> 2;
    const int lp = lane & 15, lq = lane >> 4;
    const int m0 = blockIdx.y * 128, n0 = blockIdx.x * 128;

    const __half* Ah = (MODE == 1) ? g_x_hi : g_ah_hi;
    const __half* Al = (MODE == 1) ? g_x_lo : g_ah_lo;
    const __half* Bw = (MODE == 1) ? g_wq : g_wp;

    const __half* aH = Ah + (size_t)m0 * K;
    const __half* aL = Al + (size_t)m0 * K;
    const __half* bW = Bw + (size_t)n0 * K;

    const uint32_t arow = (uint32_t)((wr*32 + lp) * 80 + lq * 16);
    const uint32_t brow = (uint32_t)((wc*64 + lp) * 80 + lq * 16);

    float acc[2][8][4];
    #pragma unroll
    for (int i = 0; i < 2; i++)
        #pragma unroll
        for (int j = 0; j < 8; j++)
            #pragma unroll
            for (int q = 0; q < 4; q++) acc[i][j][q] = 0.f;

    auto load_stage = [&](int buf, int ks) {
        const uint32_t st = sb + buf * STAGE_B;
        const int k0h = ks * 32;
        #pragma unroll
        for (int rep = 0; rep < 2; rep++) {
            const int idx = t + rep * 256;
            const int r = idx >> 2, s = idx & 3;
            const uint32_t so = (uint32_t)(r * 80 + s * 16);
            const size_t go = (size_t)r * K + k0h + s * 8;
            cpasync16(st + OFF_AH + so, aH + go);
            cpasync16(st + OFF_AL + so, aL + go);
            cpasync16(st + OFF_B  + so, bW + go);
        }
        asm volatile("cp.async.commit_group;" ::: "memory");
    };

    load_stage(0, 0);

    for (int ks = 0; ks < NSTAGE; ks++) {
        if (ks + 1 < NSTAGE) {
            load_stage((ks + 1) & 1, ks + 1);
            asm volatile("cp.async.wait_group 1;" ::: "memory");
        } else {
            asm volatile("cp.async.wait_group 0;" ::: "memory");
        }
        __syncthreads();

        const uint32_t st = sb + (ks & 1) * STAGE_B;
        #pragma unroll
        for (int kk = 0; kk < 2; kk++) {
            const uint32_t kb = kk * 32;
            uint32_t bf[4][4];
            #pragma unroll
            for (int ng = 0; ng < 4; ng++)
                ldsm4(bf[ng], st + OFF_B + brow + ng*1280 + kb);
            uint32_t ahf[2][4], alf[2][4];
            #pragma unroll
            for (int rg = 0; rg < 2; rg++) {
                ldsm4(ahf[rg], st + OFF_AH + arow + rg*1280 + kb);
                ldsm4(alf[rg], st + OFF_AL + arow + rg*1280 + kb);
            }

            // Pass 1: Ah x B   (16 MMAs, all-distinct accumulators)
            #pragma unroll
            for (int rg = 0; rg < 2; rg++)
                #pragma unroll
                for (int ng = 0; ng < 4; ng++) {
                    uint32_t b0[2] = {bf[ng][0], bf[ng][2]};
                    uint32_t b1[2] = {bf[ng][1], bf[ng][3]};
                    mma16816h(acc[rg][2*ng],   ahf[rg], b0);
                    mma16816h(acc[rg][2*ng+1], ahf[rg], b1);
                }
            // Pass 2: Al x B
            #pragma unroll
            for (int rg = 0; rg < 2; rg++)
                #pragma unroll
                for (int ng = 0; ng < 4; ng++) {
                    uint32_t b0[2] = {bf[ng][0], bf[ng][2]};
                    uint32_t b1[2] = {bf[ng][1], bf[ng][3]};
                    mma16816h(acc[rg][2*ng],   alf[rg], b0);
                    mma16816h(acc[rg][2*ng+1], alf[rg], b1);
                }
        }
        __syncthreads();
    }

    // ---- Epilogue ----
    const int gcb = n0 + wc*64;       // 64-aligned -> single head / single q|k|v
    const int lrow = lane >> 2, lc2 = 2*(lane & 3);

    if (MODE == 1) {
        const int three = gcb >> 10;
        const int h     = (gcb >> 6) & (HEADS - 1);
        #pragma unroll
        for (int rg = 0; rg < 2; rg++) {
            const int row = m0 + wr*32 + rg*16 + lrow;
            const int b = row >> 10, n = row & (SEQ - 1);
            const size_t r0i = (((size_t)(b*HEADS + h))*SEQ + n)*HD;
            const size_t r1i = r0i + (size_t)8*HD;
            #pragma unroll
            for (int ng = 0; ng < 4; ng++)
                #pragma unroll
                for (int j = 0; j < 2; j++) {
                    const int col = gcb + ng*16 + j*8 + lc2;
                    const int dd = col & 63;
                    const float b0 = bias[col], b1 = bias[col + 1];
                    float* c = acc[rg][2*ng + j];
                    if (three == 0) {          // Q: fp16 hi/lo, pre-scaled
                        uint32_t h01, l01, h23, l23;
                        split2h((c[0] + b0) * ATT_SCALE, (c[1] + b1) * ATT_SCALE, h01, l01);
                        split2h((c[2] + b0) * ATT_SCALE, (c[3] + b1) * ATT_SCALE, h23, l23);
                        *reinterpret_cast<uint32_t*>(g_qh + r0i + dd) = h01;
                        *reinterpret_cast<uint32_t*>(g_ql + r0i + dd) = l01;
                        *reinterpret_cast<uint32_t*>(g_qh + r1i + dd) = h23;
                        *reinterpret_cast<uint32_t*>(g_ql + r1i + dd) = l23;
                    } else {                   // K / V: single fp16
                        __half* dst = (three == 1) ? g_k : g_v;
                        *reinterpret_cast<uint32_t*>(dst + r0i + dd) = pack2h(c[0] + b0, c[1] + b1);
                        *reinterpret_cast<uint32_t*>(dst + r1i + dd) = pack2h(c[2] + b0, c[3] + b1);
                    }
                }
        }
    } else {
        #pragma unroll
        for (int rg = 0; rg < 2; rg++) {
            const int row = m0 + wr*32 + rg*16 + lrow;
            float* dst0 = Cout + (size_t)row * N;
            float* dst1 = Cout + (size_t)(row + 8) * N;
            #pragma unroll
            for (int ng = 0; ng < 4; ng++)
                #pragma unroll
                for (int j = 0; j < 2; j++) {
                    const int col = gcb + ng*16 + j*8 + lc2;
                    const float b0 = bias[col], b1 = bias[col + 1];
                    float* c = acc[rg][2*ng + j];
                    *reinterpret_cast<float2*>(dst0 + col) = make_float2(c[0] + b0, c[1] + b1);
                    *reinterpret_cast<float2*>(dst1 + col) = make_float2(c[2] + b0, c[3] + b1);
                }
        }
    }
}

// ---------------------------------------------------------------------------
// Flash attention, fp16 2-term: Q hi/lo fp16 split, K/V single fp16,
// P re-split fp16 hi/lo in registers. Grid (SEQ/128, B*H), 256 thr.
// smem: Qh/Ql [128][72]; per stage K[64][72] + V[64][72]; double buffered.
// ---------------------------------------------------------------------------
#define AT_T     72                        // halves per smem row (144 B)
#define AT_QH    0
#define AT_QL    18432
#define AT_STG   36864                     // first KV stage
#define AT_STGB  18432                     // stage size (K + V)
#define AT_V     9216                      // V offset within stage
#define AT_SMEM  (AT_STG + 2*AT_STGB)      // 73728 B

__global__ __launch_bounds__(256, 2)
void attn_mma()
{
    extern __shared__ char smem[];
    const uint32_t sb = smem_u32(smem);
    const int t = threadIdx.x, lane = t & 31, wid = t >> 5;
    const int bh = blockIdx.y;
    const int r0 = blockIdx.x * 128;
    const size_t bho = (size_t)bh * SEQ * HD;

    const __half* Qh = g_qh + bho + (size_t)r0 * HD;
    const __half* Ql = g_ql + bho + (size_t)r0 * HD;
    const __half* Kg = g_k + bho;
    const __half* Vg = g_v + bho;

    // Q tiles (once): 128 rows x 8 segs x {hi,lo} = 2048 cp.async transfers
    for (int i = t; i < 2048; i += 256) {
        const int tile = i >> 10, rem = i & 1023, row = rem >> 3, seg = rem & 7;
        const __half* src = (tile ? Ql : Qh) + (size_t)row * HD + seg * 8;
        cpasync16(sb + (tile ? AT_QL : AT_QH) + row*144 + seg*16, src);
    }
    auto load_stage = [&](int buf, int j0) {
        const uint32_t st = sb + AT_STG + buf * AT_STGB;
        for (int i = t; i < 1024; i += 256) {
            const int tile = i >> 9, rem = i & 511, row = rem >> 3, seg = rem & 7;
            const __half* src = (tile ? Vg : Kg) + (size_t)(j0 + row) * HD + seg * 8;
            cpasync16(st + tile*AT_V + row*144 + seg*16, src);
        }
        asm volatile("cp.async.commit_group;" ::: "memory");
    };
    load_stage(0, 0);   // commits Q too

    // ldmatrix per-thread offsets (bytes)
    const int mrow = lane & 7, mid = lane >> 3;
    const uint32_t qoff = (uint32_t)(((wid*16 + ((mid & 1) ? 8 : 0) + mrow) * AT_T
                                      + ((mid & 2) ? 8 : 0)) * 2);
    const uint32_t koff = (uint32_t)(((((mid & 2) ? 8 : 0) + mrow) * AT_T
                                      + ((mid & 1) ? 8 : 0)) * 2);
    const uint32_t voff = (uint32_t)(((((mid & 1) ? 8 : 0) + mrow) * AT_T
                                      + ((mid & 2) ? 8 : 0)) * 2);

    float o[8][4];
    #pragma unroll
    for (int i = 0; i < 8; i++)
        #pragma unroll
        for (int q = 0; q < 4; q++) o[i][q] = 0.f;
    float mA = -1e30f, mB = -1e30f, lA = 0.f, lB = 0.f;

    for (int it = 0; it < SEQ/64; it++) {
        if (it + 1 < SEQ/64) {
            load_stage((it + 1) & 1, (it + 1) * 64);
            asm volatile("cp.async.wait_group 1;" ::: "memory");
        } else {
            asm volatile("cp.async.wait_group 0;" ::: "memory");
        }
        __syncthreads();

        const uint32_t Kb = sb + AT_STG + (it & 1) * AT_STGB;
        const uint32_t Vb = Kb + AT_V;

        // ---- S = (Qh+Ql) K^T, chains interleaved across s[2j]/s[2j+1] ----
        float s[8][4];
        #pragma unroll
        for (int i = 0; i < 8; i++)
            #pragma unroll
            for (int q = 0; q < 4; q++) s[i][q] = 0.f;

        #pragma unroll
        for (int g = 0; g < 4; g++) {
            uint32_t qfh[4], qfl[4];
            ldsm4(qfh, sb + AT_QH + qoff + g*32);
            ldsm4(qfl, sb + AT_QL + qoff + g*32);
            #pragma unroll
            for (int j = 0; j < 4; j++) {
                uint32_t kf[4];
                ldsm4(kf, Kb + koff + (uint32_t)((j*16*AT_T + g*16) * 2));
                uint32_t b0[2] = {kf[0], kf[1]}, b1[2] = {kf[2], kf[3]};
                mma16816h(s[2*j],   qfh, b0);
                mma16816h(s[2*j+1], qfh, b1);
                mma16816h(s[2*j],   qfl, b0);
                mma16816h(s[2*j+1], qfl, b1);
            }
        }

        // ---- online softmax (rows: A = lane/4, B = lane/4 + 8) ----
        float mxA = s[0][0], mxB = s[0][2];
        #pragma unroll
        for (int i = 0; i < 8; i++) {
            mxA = fmaxf(mxA, fmaxf(s[i][0], s[i][1]));
            mxB = fmaxf(mxB, fmaxf(s[i][2], s[i][3]));
        }
        mxA = fmaxf(mxA, __shfl_xor_sync(0xffffffffu, mxA, 1));
        mxA = fmaxf(mxA, __shfl_xor_sync(0xffffffffu, mxA, 2));
        mxB = fmaxf(mxB, __shfl_xor_sync(0xffffffffu, mxB, 1));
        mxB = fmaxf(mxB, __shfl_xor_sync(0xffffffffu, mxB, 2));
        const float nmA = fmaxf(mA, mxA), nmB = fmaxf(mB, mxB);

        float ltA = 0.f, ltB = 0.f;
        #pragma unroll
        for (int i = 0; i < 8; i++) {
            s[i][0] = __expf(s[i][0] - nmA); ltA += s[i][0];
            s[i][1] = __expf(s[i][1] - nmA); ltA += s[i][1];
            s[i][2] = __expf(s[i][2] - nmB); ltB += s[i][2];
            s[i][3] = __expf(s[i][3] - nmB); ltB += s[i][3];
        }
        ltA += __shfl_xor_sync(0xffffffffu, ltA, 1);
        ltA += __shfl_xor_sync(0xffffffffu, ltA, 2);
        ltB += __shfl_xor_sync(0xffffffffu, ltB, 1);
        ltB += __shfl_xor_sync(0xffffffffu, ltB, 2);

        const float aA = __expf(mA - nmA), aB = __expf(mB - nmB);
        lA = lA * aA + ltA;  mA = nmA;
        lB = lB * aB + ltB;  mB = nmB;
        #pragma unroll
        for (int i = 0; i < 8; i++) {
            o[i][0] *= aA; o[i][1] *= aA;
            o[i][2] *= aB; o[i][3] *= aB;
        }

        // ---- O += (Ph+Pl) V, chains interleaved across o[2j]/o[2j+1] ----
        #pragma unroll
        for (int g = 0; g < 4; g++) {
            uint32_t ph[4], pl[4];
            split2h(s[2*g][0],   s[2*g][1],   ph[0], pl[0]);
            split2h(s[2*g][2],   s[2*g][3],   ph[1], pl[1]);
            split2h(s[2*g+1][0], s[2*g+1][1], ph[2], pl[2]);
            split2h(s[2*g+1][2], s[2*g+1][3], ph[3], pl[3]);
            #pragma unroll
            for (int j = 0; j < 4; j++) {
                uint32_t vf[4];
                ldsm4t(vf, Vb + voff + (uint32_t)((g*16*AT_T + j*16) * 2));
                uint32_t b0[2] = {vf[0], vf[1]}, b1[2] = {vf[2], vf[3]};
                mma16816h(o[2*j],   ph, b0);
                mma16816h(o[2*j+1], ph, b1);
                mma16816h(o[2*j],   pl, b0);
                mma16816h(o[2*j+1], pl, b1);
            }
        }
        __syncthreads();
    }

    // ---- epilogue: write fp16 hi/lo attention output (for fp16 proj GEMM) ----
    const float iA = 1.f / lA, iB = 1.f / lB;
    const int b = bh >> 4, h = bh & 15;
    const int nA = r0 + wid*16 + (lane >> 2), nB = nA + 8;
    const size_t baseA = ((size_t)(b*SEQ + nA))*DIM + h*HD;
    const size_t baseB = ((size_t)(b*SEQ + nB))*DIM + h*HD;
    #pragma unroll
    for (int tt = 0; tt < 8; tt++) {
        const int d = tt*8 + 2*(lane & 3);
        uint32_t hA, lAo, hB, lBo;
        split2h(o[tt][0]*iA, o[tt][1]*iA, hA, lAo);
        split2h(o[tt][2]*iB, o[tt][3]*iB, hB, lBo);
        *reinterpret_cast<uint32_t*>(g_ah_hi + baseA + d) = hA;
        *reinterpret_cast<uint32_t*>(g_ah_lo + baseA + d) = lAo;
        *reinterpret_cast<uint32_t*>(g_ah_hi + baseB + d) = hB;
        *reinterpret_cast<uint32_t*>(g_ah_lo + baseB + d) = lBo;
    }
}

// ---------------------------------------------------------------------------
extern "C" void kernel_launch(void* const* d_in, const int* in_sizes, int n_in,
                              void* d_out, int out_size)
{
    const float* x      = (const float*)d_in[0];
    const float* w_qkv  = (const float*)d_in[1];
    const float* b_qkv  = (const float*)d_in[2];
    const float* w_proj = (const float*)d_in[3];
    const float* b_proj = (const float*)d_in[4];
    float* out = (float*)d_out;

    const int gemm_smem = 2 * STAGE_B;   // 61440 B
    cudaFuncSetAttribute(mma_gemm<1>, cudaFuncAttributeMaxDynamicSharedMemorySize, gemm_smem);
    cudaFuncSetAttribute(mma_gemm<2>, cudaFuncAttributeMaxDynamicSharedMemorySize, gemm_smem);
    cudaFuncSetAttribute(attn_mma,    cudaFuncAttributeMaxDynamicSharedMemorySize, AT_SMEM);

    // 0) Prep: split x (fp16 hi/lo), transpose weights (fp16)
    split_x<<<4096, 256>>>(x, BATCH*SEQ*DIM/4);
    transpose_w<0><<<dim3(96, 32), dim3(32, 8)>>>(w_qkv);
    transpose_w<1><<<dim3(32, 32), dim3(32, 8)>>>(w_proj);

    // 1) QKV GEMM (fp16 2-term) -> Q fp16 hi/lo (pre-scaled), K/V single fp16
    mma_gemm<1><<<dim3(3*DIM/128, BATCH*SEQ/128), 256, gemm_smem>>>(b_qkv, nullptr, 3*DIM);

    // 2) Flash attention (fp16 2-term) -> fp16 hi/lo g_ah
    attn_mma<<<dim3(SEQ/128, BATCH*HEADS), 256, AT_SMEM>>>();

    // 3) Projection GEMM (fp16 2-term)
    mma_gemm<2><<<dim3(DIM/128, BATCH*SEQ/128), 256, gemm_smem>>>(b_proj, out, DIM);
}

// round 15
// speedup vs baseline: 1.6034x; 1.4477x over previous
#include <cuda_runtime.h>
#include <cuda_bf16.h>
#include <cuda_fp16.h>
#include <cstdint>
#include <math.h>

#define BATCH 4
#define HEADS 16
#define SEQ   1024
#define HD    64
#define DIM   1024
#define ATT_SCALE 0.125f   // HD^-0.5

// ---------------------------------------------------------------------------
// Device-global scratch (allocation-free per harness rules)
// ---------------------------------------------------------------------------
__device__ __align__(16) __half g_qh[BATCH*HEADS*SEQ*HD], g_ql[BATCH*HEADS*SEQ*HD];
__device__ __align__(16) __half g_k[BATCH*HEADS*SEQ*HD];   // single fp16
__device__ __align__(16) __half g_v[BATCH*HEADS*SEQ*HD];   // single fp16

__device__ __align__(16) __half g_x[BATCH*SEQ*DIM];        // single fp16 activations
__device__ __align__(16) __half g_ah[BATCH*SEQ*DIM];       // single fp16 attn output
__device__ __align__(16) __half g_wq[3*DIM*DIM];   // [N=3072][K=1024], fp16
__device__ __align__(16) __half g_wp[DIM*DIM];     // [N=1024][K=1024], fp16

// ---------------------------------------------------------------------------
// PTX helpers legal on plain compute_103 (sm_80-era instructions)
// ---------------------------------------------------------------------------
__device__ __forceinline__ uint32_t smem_u32(const void* p) {
    uint32_t a;
    asm("{ .reg .u64 t; cvta.to.shared.u64 t, %1; cvt.u32.u64 %0, t; }" : "=r"(a) : "l"(p));
    return a;
}
__device__ __forceinline__ void cpasync16(uint32_t dst, const void* src) {
    asm volatile("cp.async.cg.shared.global [%0], [%1], 16;" :: "r"(dst), "l"(src));
}
__device__ __forceinline__ void ldsm4(uint32_t* r, uint32_t addr) {
    asm volatile("ldmatrix.sync.aligned.m8n8.x4.shared.b16 {%0,%1,%2,%3}, [%4];"
        : "=r"(r[0]), "=r"(r[1]), "=r"(r[2]), "=r"(r[3]) : "r"(addr));
}
__device__ __forceinline__ void ldsm4t(uint32_t* r, uint32_t addr) {
    asm volatile("ldmatrix.sync.aligned.m8n8.x4.trans.shared.b16 {%0,%1,%2,%3}, [%4];"
        : "=r"(r[0]), "=r"(r[1]), "=r"(r[2]), "=r"(r[3]) : "r"(addr));
}
// fp16 MMA
__device__ __forceinline__ void mma16816h(float* c, const uint32_t* a, const uint32_t* b) {
    asm volatile(
        "mma.sync.aligned.m16n8k16.row.col.f32.f16.f16.f32 "
        "{%0,%1,%2,%3}, {%4,%5,%6,%7}, {%8,%9}, {%0,%1,%2,%3};"
        : "+f"(c[0]), "+f"(c[1]), "+f"(c[2]), "+f"(c[3])
        : "r"(a[0]), "r"(a[1]), "r"(a[2]), "r"(a[3]), "r"(b[0]), "r"(b[1]));
}
// fp16 hi/lo pack
__device__ __forceinline__ void split2h(float x, float y, uint32_t& hi, uint32_t& lo) {
    __half hx = __float2half_rn(x), hy = __float2half_rn(y);
    __half lx = __float2half_rn(x - __half2float(hx));
    __half ly = __float2half_rn(y - __half2float(hy));
    __half2 H = __halves2half2(hx, hy), L = __halves2half2(lx, ly);
    hi = *reinterpret_cast<uint32_t*>(&H);
    lo = *reinterpret_cast<uint32_t*>(&L);
}
__device__ __forceinline__ uint32_t pack2h(float x, float y) {
    __half2 H = __halves2half2(__float2half_rn(x), __float2half_rn(y));
    return *reinterpret_cast<uint32_t*>(&H);
}

// ---------------------------------------------------------------------------
// Prep kernels
// ---------------------------------------------------------------------------
__global__ void cast_x(const float* __restrict__ src, int n4)
{
    int i = blockIdx.x * blockDim.x + threadIdx.x;
    if (i >= n4) return;
    float4 v = reinterpret_cast<const float4*>(src)[i];
    uint32_t* p = reinterpret_cast<uint32_t*>(g_x) + i*2;
    p[0] = pack2h(v.x, v.y);
    p[1] = pack2h(v.z, v.w);
}

template<int W>     // 0: w_qkv [1024][3072], 1: w_proj [1024][1024]
__global__ void transpose_w(const float* __restrict__ src)
{
    constexpr int R = DIM;
    constexpr int C = (W == 0) ? 3*DIM : DIM;
    __half* dh = (W == 0) ? g_wq : g_wp;
    __shared__ float tile[32][33];
    const int c0 = blockIdx.x * 32, r0 = blockIdx.y * 32;
    const int x = threadIdx.x, y = threadIdx.y;  // 32 x 8
    #pragma unroll
    for (int i = 0; i < 32; i += 8)
        tile[y + i][x] = src[(size_t)(r0 + y + i) * C + c0 + x];
    __syncthreads();
    #pragma unroll
    for (int i = 0; i < 32; i += 8) {
        float v = tile[x][y + i];
        dh[(size_t)(c0 + y + i) * R + r0 + x] = __float2half_rn(v);
    }
}

// ---------------------------------------------------------------------------
// Single-fp16 GEMM: C = A @ B^T + bias (A, B both rounded fp16).
// 256 thr, 8 warps, 32x64 warp tiles, BK=32, 80B stride, double-buffered.
// MODE 1: QKV epilogue -> Q fp16 hi/lo (pre-scaled), K/V single fp16.
// MODE 2: plain fp32 epilogue (proj).
// ---------------------------------------------------------------------------
#define T_STR    40
#define TILE_B   (128*T_STR*2)           // 10240 B per 128x32 tile
#define OFF_A    0
#define OFF_B    (TILE_B)
#define STAGE_B  (2*TILE_B)              // 20480 B
#define NSTAGE   (DIM/32)

template<int MODE>
__global__ __launch_bounds__(256, 2)
void mma_gemm(const float* __restrict__ bias, float* __restrict__ Cout, int N)
{
    constexpr int K = 1024;
    extern __shared__ char smem[];
    const uint32_t sb = smem_u32(smem);

    const int t = threadIdx.x, wid = t >> 5, lane = t & 31;
    const int wr = wid & 3, wc = wid >> 2;
    const int lp = lane & 15, lq = lane >> 4;
    const int m0 = blockIdx.y * 128, n0 = blockIdx.x * 128;

    const __half* Aa = (MODE == 1) ? g_x : g_ah;
    const __half* Bw = (MODE == 1) ? g_wq : g_wp;

    const __half* aP = Aa + (size_t)m0 * K;
    const __half* bW = Bw + (size_t)n0 * K;

    const uint32_t arow = (uint32_t)((wr*32 + lp) * 80 + lq * 16);
    const uint32_t brow = (uint32_t)((wc*64 + lp) * 80 + lq * 16);

    float acc[2][8][4];
    #pragma unroll
    for (int i = 0; i < 2; i++)
        #pragma unroll
        for (int j = 0; j < 8; j++)
            #pragma unroll
            for (int q = 0; q < 4; q++) acc[i][j][q] = 0.f;

    auto load_stage = [&](int buf, int ks) {
        const uint32_t st = sb + buf * STAGE_B;
        const int k0h = ks * 32;
        #pragma unroll
        for (int rep = 0; rep < 2; rep++) {
            const int idx = t + rep * 256;
            const int r = idx >> 2, s = idx & 3;
            const uint32_t so = (uint32_t)(r * 80 + s * 16);
            const size_t go = (size_t)r * K + k0h + s * 8;
            cpasync16(st + OFF_A + so, aP + go);
            cpasync16(st + OFF_B + so, bW + go);
        }
        asm volatile("cp.async.commit_group;" ::: "memory");
    };

    load_stage(0, 0);

    for (int ks = 0; ks < NSTAGE; ks++) {
        if (ks + 1 < NSTAGE) {
            load_stage((ks + 1) & 1, ks + 1);
            asm volatile("cp.async.wait_group 1;" ::: "memory");
        } else {
            asm volatile("cp.async.wait_group 0;" ::: "memory");
        }
        __syncthreads();

        const uint32_t st = sb + (ks & 1) * STAGE_B;
        #pragma unroll
        for (int kk = 0; kk < 2; kk++) {
            const uint32_t kb = kk * 32;
            uint32_t bf[4][4];
            #pragma unroll
            for (int ng = 0; ng < 4; ng++)
                ldsm4(bf[ng], st + OFF_B + brow + ng*1280 + kb);
            uint32_t af[2][4];
            #pragma unroll
            for (int rg = 0; rg < 2; rg++)
                ldsm4(af[rg], st + OFF_A + arow + rg*1280 + kb);

            // 16 MMAs, all-distinct accumulators
            #pragma unroll
            for (int rg = 0; rg < 2; rg++)
                #pragma unroll
                for (int ng = 0; ng < 4; ng++) {
                    uint32_t b0[2] = {bf[ng][0], bf[ng][2]};
                    uint32_t b1[2] = {bf[ng][1], bf[ng][3]};
                    mma16816h(acc[rg][2*ng],   af[rg], b0);
                    mma16816h(acc[rg][2*ng+1], af[rg], b1);
                }
        }
        __syncthreads();
    }

    // ---- Epilogue ----
    const int gcb = n0 + wc*64;       // 64-aligned -> single head / single q|k|v
    const int lrow = lane >> 2, lc2 = 2*(lane & 3);

    if (MODE == 1) {
        const int three = gcb >> 10;
        const int h     = (gcb >> 6) & (HEADS - 1);
        #pragma unroll
        for (int rg = 0; rg < 2; rg++) {
            const int row = m0 + wr*32 + rg*16 + lrow;
            const int b = row >> 10, n = row & (SEQ - 1);
            const size_t r0i = (((size_t)(b*HEADS + h))*SEQ + n)*HD;
            const size_t r1i = r0i + (size_t)8*HD;
            #pragma unroll
            for (int ng = 0; ng < 4; ng++)
                #pragma unroll
                for (int j = 0; j < 2; j++) {
                    const int col = gcb + ng*16 + j*8 + lc2;
                    const int dd = col & 63;
                    const float b0 = bias[col], b1 = bias[col + 1];
                    float* c = acc[rg][2*ng + j];
                    if (three == 0) {          // Q: fp16 hi/lo, pre-scaled
                        uint32_t h01, l01, h23, l23;
                        split2h((c[0] + b0) * ATT_SCALE, (c[1] + b1) * ATT_SCALE, h01, l01);
                        split2h((c[2] + b0) * ATT_SCALE, (c[3] + b1) * ATT_SCALE, h23, l23);
                        *reinterpret_cast<uint32_t*>(g_qh + r0i + dd) = h01;
                        *reinterpret_cast<uint32_t*>(g_ql + r0i + dd) = l01;
                        *reinterpret_cast<uint32_t*>(g_qh + r1i + dd) = h23;
                        *reinterpret_cast<uint32_t*>(g_ql + r1i + dd) = l23;
                    } else {                   // K / V: single fp16
                        __half* dst = (three == 1) ? g_k : g_v;
                        *reinterpret_cast<uint32_t*>(dst + r0i + dd) = pack2h(c[0] + b0, c[1] + b1);
                        *reinterpret_cast<uint32_t*>(dst + r1i + dd) = pack2h(c[2] + b0, c[3] + b1);
                    }
                }
        }
    } else {
        #pragma unroll
        for (int rg = 0; rg < 2; rg++) {
            const int row = m0 + wr*32 + rg*16 + lrow;
            float* dst0 = Cout + (size_t)row * N;
            float* dst1 = Cout + (size_t)(row + 8) * N;
            #pragma unroll
            for (int ng = 0; ng < 4; ng++)
                #pragma unroll
                for (int j = 0; j < 2; j++) {
                    const int col = gcb + ng*16 + j*8 + lc2;
                    const float b0 = bias[col], b1 = bias[col + 1];
                    float* c = acc[rg][2*ng + j];
                    *reinterpret_cast<float2*>(dst0 + col) = make_float2(c[0] + b0, c[1] + b1);
                    *reinterpret_cast<float2*>(dst1 + col) = make_float2(c[2] + b0, c[3] + b1);
                }
        }
    }
}

// ---------------------------------------------------------------------------
// Flash attention (R14, unchanged math): Q hi/lo fp16, K/V single fp16,
// P hi/lo fp16. Epilogue now writes single fp16 g_ah.
// Grid (SEQ/128, B*H), 256 thr.
// ---------------------------------------------------------------------------
#define AT_T     72                        // halves per smem row (144 B)
#define AT_QH    0
#define AT_QL    18432
#define AT_STG   36864                     // first KV stage
#define AT_STGB  18432                     // stage size (K + V)
#define AT_V     9216                      // V offset within stage
#define AT_SMEM  (AT_STG + 2*AT_STGB)      // 73728 B

__global__ __launch_bounds__(256, 2)
void attn_mma()
{
    extern __shared__ char smem[];
    const uint32_t sb = smem_u32(smem);
    const int t = threadIdx.x, lane = t & 31, wid = t >> 5;
    const int bh = blockIdx.y;
    const int r0 = blockIdx.x * 128;
    const size_t bho = (size_t)bh * SEQ * HD;

    const __half* Qh = g_qh + bho + (size_t)r0 * HD;
    const __half* Ql = g_ql + bho + (size_t)r0 * HD;
    const __half* Kg = g_k + bho;
    const __half* Vg = g_v + bho;

    // Q tiles (once): 128 rows x 8 segs x {hi,lo} = 2048 cp.async transfers
    for (int i = t; i < 2048; i += 256) {
        const int tile = i >> 10, rem = i & 1023, row = rem >> 3, seg = rem & 7;
        const __half* src = (tile ? Ql : Qh) + (size_t)row * HD + seg * 8;
        cpasync16(sb + (tile ? AT_QL : AT_QH) + row*144 + seg*16, src);
    }
    auto load_stage = [&](int buf, int j0) {
        const uint32_t st = sb + AT_STG + buf * AT_STGB;
        for (int i = t; i < 1024; i += 256) {
            const int tile = i >> 9, rem = i & 511, row = rem >> 3, seg = rem & 7;
            const __half* src = (tile ? Vg : Kg) + (size_t)(j0 + row) * HD + seg * 8;
            cpasync16(st + tile*AT_V + row*144 + seg*16, src);
        }
        asm volatile("cp.async.commit_group;" ::: "memory");
    };
    load_stage(0, 0);   // commits Q too

    // ldmatrix per-thread offsets (bytes)
    const int mrow = lane & 7, mid = lane >> 3;
    const uint32_t qoff = (uint32_t)(((wid*16 + ((mid & 1) ? 8 : 0) + mrow) * AT_T
                                      + ((mid & 2) ? 8 : 0)) * 2);
    const uint32_t koff = (uint32_t)(((((mid & 2) ? 8 : 0) + mrow) * AT_T
                                      + ((mid & 1) ? 8 : 0)) * 2);
    const uint32_t voff = (uint32_t)(((((mid & 1) ? 8 : 0) + mrow) * AT_T
                                      + ((mid & 2) ? 8 : 0)) * 2);

    float o[8][4];
    #pragma unroll
    for (int i = 0; i < 8; i++)
        #pragma unroll
        for (int q = 0; q < 4; q++) o[i][q] = 0.f;
    float mA = -1e30f, mB = -1e30f, lA = 0.f, lB = 0.f;

    for (int it = 0; it < SEQ/64; it++) {
        if (it + 1 < SEQ/64) {
            load_stage((it + 1) & 1, (it + 1) * 64);
            asm volatile("cp.async.wait_group 1;" ::: "memory");
        } else {
            asm volatile("cp.async.wait_group 0;" ::: "memory");
        }
        __syncthreads();

        const uint32_t Kb = sb + AT_STG + (it & 1) * AT_STGB;
        const uint32_t Vb = Kb + AT_V;

        // ---- S = (Qh+Ql) K^T, chains interleaved across s[2j]/s[2j+1] ----
        float s[8][4];
        #pragma unroll
        for (int i = 0; i < 8; i++)
            #pragma unroll
            for (int q = 0; q < 4; q++) s[i][q] = 0.f;

        #pragma unroll
        for (int g = 0; g < 4; g++) {
            uint32_t qfh[4], qfl[4];
            ldsm4(qfh, sb + AT_QH + qoff + g*32);
            ldsm4(qfl, sb + AT_QL + qoff + g*32);
            #pragma unroll
            for (int j = 0; j < 4; j++) {
                uint32_t kf[4];
                ldsm4(kf, Kb + koff + (uint32_t)((j*16*AT_T + g*16) * 2));
                uint32_t b0[2] = {kf[0], kf[1]}, b1[2] = {kf[2], kf[3]};
                mma16816h(s[2*j],   qfh, b0);
                mma16816h(s[2*j+1], qfh, b1);
                mma16816h(s[2*j],   qfl, b0);
                mma16816h(s[2*j+1], qfl, b1);
            }
        }

        // ---- online softmax (rows: A = lane/4, B = lane/4 + 8) ----
        float mxA = s[0][0], mxB = s[0][2];
        #pragma unroll
        for (int i = 0; i < 8; i++) {
            mxA = fmaxf(mxA, fmaxf(s[i][0], s[i][1]));
            mxB = fmaxf(mxB, fmaxf(s[i][2], s[i][3]));
        }
        mxA = fmaxf(mxA, __shfl_xor_sync(0xffffffffu, mxA, 1));
        mxA = fmaxf(mxA, __shfl_xor_sync(0xffffffffu, mxA, 2));
        mxB = fmaxf(mxB, __shfl_xor_sync(0xffffffffu, mxB, 1));
        mxB = fmaxf(mxB, __shfl_xor_sync(0xffffffffu, mxB, 2));
        const float nmA = fmaxf(mA, mxA), nmB = fmaxf(mB, mxB);

        float ltA = 0.f, ltB = 0.f;
        #pragma unroll
        for (int i = 0; i < 8; i++) {
            s[i][0] = __expf(s[i][0] - nmA); ltA += s[i][0];
            s[i][1] = __expf(s[i][1] - nmA); ltA += s[i][1];
            s[i][2] = __expf(s[i][2] - nmB); ltB += s[i][2];
            s[i][3] = __expf(s[i][3] - nmB); ltB += s[i][3];
        }
        ltA += __shfl_xor_sync(0xffffffffu, ltA, 1);
        ltA += __shfl_xor_sync(0xffffffffu, ltA, 2);
        ltB += __shfl_xor_sync(0xffffffffu, ltB, 1);
        ltB += __shfl_xor_sync(0xffffffffu, ltB, 2);

        const float aA = __expf(mA - nmA), aB = __expf(mB - nmB);
        lA = lA * aA + ltA;  mA = nmA;
        lB = lB * aB + ltB;  mB = nmB;
        #pragma unroll
        for (int i = 0; i < 8; i++) {
            o[i][0] *= aA; o[i][1] *= aA;
            o[i][2] *= aB; o[i][3] *= aB;
        }

        // ---- O += (Ph+Pl) V, chains interleaved across o[2j]/o[2j+1] ----
        #pragma unroll
        for (int g = 0; g < 4; g++) {
            uint32_t ph[4], pl[4];
            split2h(s[2*g][0],   s[2*g][1],   ph[0], pl[0]);
            split2h(s[2*g][2],   s[2*g][3],   ph[1], pl[1]);
            split2h(s[2*g+1][0], s[2*g+1][1], ph[2], pl[2]);
            split2h(s[2*g+1][2], s[2*g+1][3], ph[3], pl[3]);
            #pragma unroll
            for (int j = 0; j < 4; j++) {
                uint32_t vf[4];
                ldsm4t(vf, Vb + voff + (uint32_t)((g*16*AT_T + j*16) * 2));
                uint32_t b0[2] = {vf[0], vf[1]}, b1[2] = {vf[2], vf[3]};
                mma16816h(o[2*j],   ph, b0);
                mma16816h(o[2*j+1], ph, b1);
                mma16816h(o[2*j],   pl, b0);
                mma16816h(o[2*j+1], pl, b1);
            }
        }
        __syncthreads();
    }

    // ---- epilogue: write single fp16 attention output (for fp16 proj GEMM) ----
    const float iA = 1.f / lA, iB = 1.f / lB;
    const int b = bh >> 4, h = bh & 15;
    const int nA = r0 + wid*16 + (lane >> 2), nB = nA + 8;
    const size_t baseA = ((size_t)(b*SEQ + nA))*DIM + h*HD;
    const size_t baseB = ((size_t)(b*SEQ + nB))*DIM + h*HD;
    #pragma unroll
    for (int tt = 0; tt < 8; tt++) {
        const int d = tt*8 + 2*(lane & 3);
        *reinterpret_cast<uint32_t*>(g_ah + baseA + d) = pack2h(o[tt][0]*iA, o[tt][1]*iA);
        *reinterpret_cast<uint32_t*>(g_ah + baseB + d) = pack2h(o[tt][2]*iB, o[tt][3]*iB);
    }
}

// ---------------------------------------------------------------------------
extern "C" void kernel_launch(void* const* d_in, const int* in_sizes, int n_in,
                              void* d_out, int out_size)
{
    const float* x      = (const float*)d_in[0];
    const float* w_qkv  = (const float*)d_in[1];
    const float* b_qkv  = (const float*)d_in[2];
    const float* w_proj = (const float*)d_in[3];
    const float* b_proj = (const float*)d_in[4];
    float* out = (float*)d_out;

    const int gemm_smem = 2 * STAGE_B;   // 40960 B
    cudaFuncSetAttribute(mma_gemm<1>, cudaFuncAttributeMaxDynamicSharedMemorySize, gemm_smem);
    cudaFuncSetAttribute(mma_gemm<2>, cudaFuncAttributeMaxDynamicSharedMemorySize, gemm_smem);
    cudaFuncSetAttribute(attn_mma,    cudaFuncAttributeMaxDynamicSharedMemorySize, AT_SMEM);

    // 0) Prep: cast x to fp16, transpose weights (fp16)
    cast_x<<<4096, 256>>>(x, BATCH*SEQ*DIM/4);
    transpose_w<0><<<dim3(96, 32), dim3(32, 8)>>>(w_qkv);
    transpose_w<1><<<dim3(32, 32), dim3(32, 8)>>>(w_proj);

    // 1) QKV GEMM (single fp16) -> Q fp16 hi/lo (pre-scaled), K/V single fp16
    mma_gemm<1><<<dim3(3*DIM/128, BATCH*SEQ/128), 256, gemm_smem>>>(b_qkv, nullptr, 3*DIM);

    // 2) Flash attention (fp16 2-term) -> single fp16 g_ah
    attn_mma<<<dim3(SEQ/128, BATCH*HEADS), 256, AT_SMEM>>>();

    // 3) Projection GEMM (single fp16)
    mma_gemm<2><<<dim3(DIM/128, BATCH*SEQ/128), 256, gemm_smem>>>(b_proj, out, DIM);
}

// round 17
// speedup vs baseline: 1.8551x; 1.1570x over previous
#include <cuda_runtime.h>
#include <cuda_bf16.h>
#include <cuda_fp16.h>
#include <cstdint>
#include <math.h>

#define BATCH 4
#define HEADS 16
#define SEQ   1024
#define HD    64
#define DIM   1024
#define ATT_SCALE 0.125f   // HD^-0.5

// ---------------------------------------------------------------------------
// Device-global scratch (allocation-free per harness rules)
// ---------------------------------------------------------------------------
__device__ __align__(16) __half g_q[BATCH*HEADS*SEQ*HD];   // single fp16, pre-scaled
__device__ __align__(16) __half g_k[BATCH*HEADS*SEQ*HD];   // single fp16
__device__ __align__(16) __half g_v[BATCH*HEADS*SEQ*HD];   // single fp16

__device__ __align__(16) __half g_x[BATCH*SEQ*DIM];        // single fp16 activations
__device__ __align__(16) __half g_ah[BATCH*SEQ*DIM];       // single fp16 attn output
__device__ __align__(16) __half g_wq[3*DIM*DIM];   // [N=3072][K=1024], fp16
__device__ __align__(16) __half g_wp[DIM*DIM];     // [N=1024][K=1024], fp16

// ---------------------------------------------------------------------------
// PTX helpers legal on plain compute_103 (sm_80-era instructions)
// ---------------------------------------------------------------------------
__device__ __forceinline__ uint32_t smem_u32(const void* p) {
    uint32_t a;
    asm("{ .reg .u64 t; cvta.to.shared.u64 t, %1; cvt.u32.u64 %0, t; }" : "=r"(a) : "l"(p));
    return a;
}
__device__ __forceinline__ void cpasync16(uint32_t dst, const void* src) {
    asm volatile("cp.async.cg.shared.global [%0], [%1], 16;" :: "r"(dst), "l"(src));
}
__device__ __forceinline__ void ldsm4(uint32_t* r, uint32_t addr) {
    asm volatile("ldmatrix.sync.aligned.m8n8.x4.shared.b16 {%0,%1,%2,%3}, [%4];"
        : "=r"(r[0]), "=r"(r[1]), "=r"(r[2]), "=r"(r[3]) : "r"(addr));
}
__device__ __forceinline__ void ldsm4t(uint32_t* r, uint32_t addr) {
    asm volatile("ldmatrix.sync.aligned.m8n8.x4.trans.shared.b16 {%0,%1,%2,%3}, [%4];"
        : "=r"(r[0]), "=r"(r[1]), "=r"(r[2]), "=r"(r[3]) : "r"(addr));
}
// fp16 MMA
__device__ __forceinline__ void mma16816h(float* c, const uint32_t* a, const uint32_t* b) {
    asm volatile(
        "mma.sync.aligned.m16n8k16.row.col.f32.f16.f16.f32 "
        "{%0,%1,%2,%3}, {%4,%5,%6,%7}, {%8,%9}, {%0,%1,%2,%3};"
        : "+f"(c[0]), "+f"(c[1]), "+f"(c[2]), "+f"(c[3])
        : "r"(a[0]), "r"(a[1]), "r"(a[2]), "r"(a[3]), "r"(b[0]), "r"(b[1]));
}
__device__ __forceinline__ uint32_t pack2h(float x, float y) {
    __half2 H = __halves2half2(__float2half_rn(x), __float2half_rn(y));
    return *reinterpret_cast<uint32_t*>(&H);
}

// ---------------------------------------------------------------------------
// Prep kernels
// ---------------------------------------------------------------------------
__global__ void cast_x(const float* __restrict__ src, int n4)
{
    int i = blockIdx.x * blockDim.x + threadIdx.x;
    if (i >= n4) return;
    float4 v = reinterpret_cast<const float4*>(src)[i];
    uint32_t* p = reinterpret_cast<uint32_t*>(g_x) + i*2;
    p[0] = pack2h(v.x, v.y);
    p[1] = pack2h(v.z, v.w);
}

template<int W>     // 0: w_qkv [1024][3072], 1: w_proj [1024][1024]
__global__ void transpose_w(const float* __restrict__ src)
{
    constexpr int R = DIM;
    constexpr int C = (W == 0) ? 3*DIM : DIM;
    __half* dh = (W == 0) ? g_wq : g_wp;
    __shared__ float tile[32][33];
    const int c0 = blockIdx.x * 32, r0 = blockIdx.y * 32;
    const int x = threadIdx.x, y = threadIdx.y;  // 32 x 8
    #pragma unroll
    for (int i = 0; i < 32; i += 8)
        tile[y + i][x] = src[(size_t)(r0 + y + i) * C + c0 + x];
    __syncthreads();
    #pragma unroll
    for (int i = 0; i < 32; i += 8) {
        float v = tile[x][y + i];
        dh[(size_t)(c0 + y + i) * R + r0 + x] = __float2half_rn(v);
    }
}

// ---------------------------------------------------------------------------
// Single-fp16 GEMM: C = A @ B^T + bias.
// 256 thr, 8 warps, 32x64 warp tiles, BK=32, 80B stride, double-buffered.
// MODE 1: QKV epilogue -> Q (pre-scaled) / K / V, all single fp16.
// MODE 2: plain fp32 epilogue (proj).
// ---------------------------------------------------------------------------
#define T_STR    40
#define TILE_B   (128*T_STR*2)           // 10240 B per 128x32 tile
#define OFF_A    0
#define OFF_B    (TILE_B)
#define STAGE_B  (2*TILE_B)              // 20480 B
#define NSTAGE   (DIM/32)

template<int MODE>
__global__ __launch_bounds__(256, 2)
void mma_gemm(const float* __restrict__ bias, float* __restrict__ Cout, int N)
{
    constexpr int K = 1024;
    extern __shared__ char smem[];
    const uint32_t sb = smem_u32(smem);

    const int t = threadIdx.x, wid = t >> 5, lane = t & 31;
    const int wr = wid & 3, wc = wid >> 2;
    const int lp = lane & 15, lq = lane >> 4;
    const int m0 = blockIdx.y * 128, n0 = blockIdx.x * 128;

    const __half* Aa = (MODE == 1) ? g_x : g_ah;
    const __half* Bw = (MODE == 1) ? g_wq : g_wp;

    const __half* aP = Aa + (size_t)m0 * K;
    const __half* bW = Bw + (size_t)n0 * K;

    const uint32_t arow = (uint32_t)((wr*32 + lp) * 80 + lq * 16);
    const uint32_t brow = (uint32_t)((wc*64 + lp) * 80 + lq * 16);

    float acc[2][8][4];
    #pragma unroll
    for (int i = 0; i < 2; i++)
        #pragma unroll
        for (int j = 0; j < 8; j++)
            #pragma unroll
            for (int q = 0; q < 4; q++) acc[i][j][q] = 0.f;

    auto load_stage = [&](int buf, int ks) {
        const uint32_t st = sb + buf * STAGE_B;
        const int k0h = ks * 32;
        #pragma unroll
        for (int rep = 0; rep < 2; rep++) {
            const int idx = t + rep * 256;
            const int r = idx >> 2, s = idx & 3;
            const uint32_t so = (uint32_t)(r * 80 + s * 16);
            const size_t go = (size_t)r * K + k0h + s * 8;
            cpasync16(st + OFF_A + so, aP + go);
            cpasync16(st + OFF_B + so, bW + go);
        }
        asm volatile("cp.async.commit_group;" ::: "memory");
    };

    load_stage(0, 0);

    for (int ks = 0; ks < NSTAGE; ks++) {
        if (ks + 1 < NSTAGE) {
            load_stage((ks + 1) & 1, ks + 1);
            asm volatile("cp.async.wait_group 1;" ::: "memory");
        } else {
            asm volatile("cp.async.wait_group 0;" ::: "memory");
        }
        __syncthreads();

        const uint32_t st = sb + (ks & 1) * STAGE_B;
        #pragma unroll
        for (int kk = 0; kk < 2; kk++) {
            const uint32_t kb = kk * 32;
            uint32_t bf[4][4];
            #pragma unroll
            for (int ng = 0; ng < 4; ng++)
                ldsm4(bf[ng], st + OFF_B + brow + ng*1280 + kb);
            uint32_t af[2][4];
            #pragma unroll
            for (int rg = 0; rg < 2; rg++)
                ldsm4(af[rg], st + OFF_A + arow + rg*1280 + kb);

            #pragma unroll
            for (int rg = 0; rg < 2; rg++)
                #pragma unroll
                for (int ng = 0; ng < 4; ng++) {
                    uint32_t b0[2] = {bf[ng][0], bf[ng][2]};
                    uint32_t b1[2] = {bf[ng][1], bf[ng][3]};
                    mma16816h(acc[rg][2*ng],   af[rg], b0);
                    mma16816h(acc[rg][2*ng+1], af[rg], b1);
                }
        }
        __syncthreads();
    }

    // ---- Epilogue ----
    const int gcb = n0 + wc*64;       // 64-aligned -> single head / single q|k|v
    const int lrow = lane >> 2, lc2 = 2*(lane & 3);

    if (MODE == 1) {
        const int three = gcb >> 10;
        const int h     = (gcb >> 6) & (HEADS - 1);
        __half* dst = (three == 0) ? g_q : (three == 1) ? g_k : g_v;
        const float sc = (three == 0) ? ATT_SCALE : 1.0f;
        #pragma unroll
        for (int rg = 0; rg < 2; rg++) {
            const int row = m0 + wr*32 + rg*16 + lrow;
            const int b = row >> 10, n = row & (SEQ - 1);
            const size_t r0i = (((size_t)(b*HEADS + h))*SEQ + n)*HD;
            const size_t r1i = r0i + (size_t)8*HD;
            #pragma unroll
            for (int ng = 0; ng < 4; ng++)
                #pragma unroll
                for (int j = 0; j < 2; j++) {
                    const int col = gcb + ng*16 + j*8 + lc2;
                    const int dd = col & 63;
                    const float b0 = bias[col], b1 = bias[col + 1];
                    float* c = acc[rg][2*ng + j];
                    *reinterpret_cast<uint32_t*>(dst + r0i + dd) =
                        pack2h((c[0] + b0) * sc, (c[1] + b1) * sc);
                    *reinterpret_cast<uint32_t*>(dst + r1i + dd) =
                        pack2h((c[2] + b0) * sc, (c[3] + b1) * sc);
                }
        }
    } else {
        #pragma unroll
        for (int rg = 0; rg < 2; rg++) {
            const int row = m0 + wr*32 + rg*16 + lrow;
            float* dst0 = Cout + (size_t)row * N;
            float* dst1 = Cout + (size_t)(row + 8) * N;
            #pragma unroll
            for (int ng = 0; ng < 4; ng++)
                #pragma unroll
                for (int j = 0; j < 2; j++) {
                    const int col = gcb + ng*16 + j*8 + lc2;
                    const float b0 = bias[col], b1 = bias[col + 1];
                    float* c = acc[rg][2*ng + j];
                    *reinterpret_cast<float2*>(dst0 + col) = make_float2(c[0] + b0, c[1] + b1);
                    *reinterpret_cast<float2*>(dst1 + col) = make_float2(c[2] + b0, c[3] + b1);
                }
        }
    }
}

// ---------------------------------------------------------------------------
// Flash attention, fully single-fp16: Q, K, V, P all single fp16.
// Grid (SEQ/128, B*H), 256 thr (8 warps x m16 rows). Bc=64 keys/iter.
// smem: Q [128][72]; per stage K[64][72] + V[64][72]; double buffered.
// ---------------------------------------------------------------------------
#define AT_T     72                        // halves per smem row (144 B)
#define AT_Q     0
#define AT_STG   18432                     // first KV stage
#define AT_STGB  18432                     // stage size (K + V)
#define AT_V     9216                      // V offset within stage
#define AT_SMEM  (AT_STG + 2*AT_STGB)      // 55296 B

__global__ __launch_bounds__(256, 2)
void attn_mma()
{
    extern __shared__ char smem[];
    const uint32_t sb = smem_u32(smem);
    const int t = threadIdx.x, lane = t & 31, wid = t >> 5;
    const int bh = blockIdx.y;
    const int r0 = blockIdx.x * 128;
    const size_t bho = (size_t)bh * SEQ * HD;

    const __half* Qg = g_q + bho + (size_t)r0 * HD;
    const __half* Kg = g_k + bho;
    const __half* Vg = g_v + bho;

    // Q tile (once): 128 rows x 8 segs = 1024 cp.async transfers
    for (int i = t; i < 1024; i += 256) {
        const int row = i >> 3, seg = i & 7;
        cpasync16(sb + AT_Q + row*144 + seg*16, Qg + (size_t)row * HD + seg * 8);
    }
    auto load_stage = [&](int buf, int j0) {
        const uint32_t st = sb + AT_STG + buf * AT_STGB;
        for (int i = t; i < 1024; i += 256) {
            const int tile = i >> 9, rem = i & 511, row = rem >> 3, seg = rem & 7;
            const __half* src = (tile ? Vg : Kg) + (size_t)(j0 + row) * HD + seg * 8;
            cpasync16(st + tile*AT_V + row*144 + seg*16, src);
        }
        asm volatile("cp.async.commit_group;" ::: "memory");
    };
    load_stage(0, 0);   // commits Q too

    // ldmatrix per-thread offsets (bytes)
    const int mrow = lane & 7, mid = lane >> 3;
    const uint32_t qoff = (uint32_t)(((wid*16 + ((mid & 1) ? 8 : 0) + mrow) * AT_T
                                      + ((mid & 2) ? 8 : 0)) * 2);
    const uint32_t koff = (uint32_t)(((((mid & 2) ? 8 : 0) + mrow) * AT_T
                                      + ((mid & 1) ? 8 : 0)) * 2);
    const uint32_t voff = (uint32_t)(((((mid & 1) ? 8 : 0) + mrow) * AT_T
                                      + ((mid & 2) ? 8 : 0)) * 2);

    float o[8][4];
    #pragma unroll
    for (int i = 0; i < 8; i++)
        #pragma unroll
        for (int q = 0; q < 4; q++) o[i][q] = 0.f;
    float mA = -1e30f, mB = -1e30f, lA = 0.f, lB = 0.f;

    for (int it = 0; it < SEQ/64; it++) {
        if (it + 1 < SEQ/64) {
            load_stage((it + 1) & 1, (it + 1) * 64);
            asm volatile("cp.async.wait_group 1;" ::: "memory");
        } else {
            asm volatile("cp.async.wait_group 0;" ::: "memory");
        }
        __syncthreads();

        const uint32_t Kb = sb + AT_STG + (it & 1) * AT_STGB;
        const uint32_t Vb = Kb + AT_V;

        // ---- S = Q K^T ----
        float s[8][4];
        #pragma unroll
        for (int i = 0; i < 8; i++)
            #pragma unroll
            for (int q = 0; q < 4; q++) s[i][q] = 0.f;

        #pragma unroll
        for (int g = 0; g < 4; g++) {
            uint32_t qf[4];
            ldsm4(qf, sb + AT_Q + qoff + g*32);
            #pragma unroll
            for (int j = 0; j < 4; j++) {
                uint32_t kf[4];
                ldsm4(kf, Kb + koff + (uint32_t)((j*16*AT_T + g*16) * 2));
                uint32_t b0[2] = {kf[0], kf[1]}, b1[2] = {kf[2], kf[3]};
                mma16816h(s[2*j],   qf, b0);
                mma16816h(s[2*j+1], qf, b1);
            }
        }

        // ---- online softmax (rows: A = lane/4, B = lane/4 + 8) ----
        float mxA = s[0][0], mxB = s[0][2];
        #pragma unroll
        for (int i = 0; i < 8; i++) {
            mxA = fmaxf(mxA, fmaxf(s[i][0], s[i][1]));
            mxB = fmaxf(mxB, fmaxf(s[i][2], s[i][3]));
        }
        mxA = fmaxf(mxA, __shfl_xor_sync(0xffffffffu, mxA, 1));
        mxA = fmaxf(mxA, __shfl_xor_sync(0xffffffffu, mxA, 2));
        mxB = fmaxf(mxB, __shfl_xor_sync(0xffffffffu, mxB, 1));
        mxB = fmaxf(mxB, __shfl_xor_sync(0xffffffffu, mxB, 2));
        const float nmA = fmaxf(mA, mxA), nmB = fmaxf(mB, mxB);

        float ltA = 0.f, ltB = 0.f;
        #pragma unroll
        for (int i = 0; i < 8; i++) {
            s[i][0] = __expf(s[i][0] - nmA); ltA += s[i][0];
            s[i][1] = __expf(s[i][1] - nmA); ltA += s[i][1];
            s[i][2] = __expf(s[i][2] - nmB); ltB += s[i][2];
            s[i][3] = __expf(s[i][3] - nmB); ltB += s[i][3];
        }
        ltA += __shfl_xor_sync(0xffffffffu, ltA, 1);
        ltA += __shfl_xor_sync(0xffffffffu, ltA, 2);
        ltB += __shfl_xor_sync(0xffffffffu, ltB, 1);
        ltB += __shfl_xor_sync(0xffffffffu, ltB, 2);

        const float aA = __expf(mA - nmA), aB = __expf(mB - nmB);
        lA = lA * aA + ltA;  mA = nmA;
        lB = lB * aB + ltB;  mB = nmB;
        #pragma unroll
        for (int i = 0; i < 8; i++) {
            o[i][0] *= aA; o[i][1] *= aA;
            o[i][2] *= aB; o[i][3] *= aB;
        }

        // ---- O += P V (P single fp16) ----
        #pragma unroll
        for (int g = 0; g < 4; g++) {
            uint32_t ph[4];
            ph[0] = pack2h(s[2*g][0],   s[2*g][1]);
            ph[1] = pack2h(s[2*g][2],   s[2*g][3]);
            ph[2] = pack2h(s[2*g+1][0], s[2*g+1][1]);
            ph[3] = pack2h(s[2*g+1][2], s[2*g+1][3]);
            #pragma unroll
            for (int j = 0; j < 4; j++) {
                uint32_t vf[4];
                ldsm4t(vf, Vb + voff + (uint32_t)((g*16*AT_T + j*16) * 2));
                uint32_t b0[2] = {vf[0], vf[1]}, b1[2] = {vf[2], vf[3]};
                mma16816h(o[2*j],   ph, b0);
                mma16816h(o[2*j+1], ph, b1);
            }
        }
        __syncthreads();
    }

    // ---- epilogue: write single fp16 attention output ----
    const float iA = 1.f / lA, iB = 1.f / lB;
    const int b = bh >> 4, h = bh & 15;
    const int nA = r0 + wid*16 + (lane >> 2), nB = nA + 8;
    const size_t baseA = ((size_t)(b*SEQ + nA))*DIM + h*HD;
    const size_t baseB = ((size_t)(b*SEQ + nB))*DIM + h*HD;
    #pragma unroll
    for (int tt = 0; tt < 8; tt++) {
        const int d = tt*8 + 2*(lane & 3);
        *reinterpret_cast<uint32_t*>(g_ah + baseA + d) = pack2h(o[tt][0]*iA, o[tt][1]*iA);
        *reinterpret_cast<uint32_t*>(g_ah + baseB + d) = pack2h(o[tt][2]*iB, o[tt][3]*iB);
    }
}

// ---------------------------------------------------------------------------
extern "C" void kernel_launch(void* const* d_in, const int* in_sizes, int n_in,
                              void* d_out, int out_size)
{
    const float* x      = (const float*)d_in[0];
    const float* w_qkv  = (const float*)d_in[1];
    const float* b_qkv  = (const float*)d_in[2];
    const float* w_proj = (const float*)d_in[3];
    const float* b_proj = (const float*)d_in[4];
    float* out = (float*)d_out;

    const int gemm_smem = 2 * STAGE_B;   // 40960 B
    cudaFuncSetAttribute(mma_gemm<1>, cudaFuncAttributeMaxDynamicSharedMemorySize, gemm_smem);
    cudaFuncSetAttribute(mma_gemm<2>, cudaFuncAttributeMaxDynamicSharedMemorySize, gemm_smem);
    cudaFuncSetAttribute(attn_mma,    cudaFuncAttributeMaxDynamicSharedMemorySize, AT_SMEM);

    // 0) Prep: cast x to fp16, transpose weights (fp16)
    cast_x<<<4096, 256>>>(x, BATCH*SEQ*DIM/4);
    transpose_w<0><<<dim3(96, 32), dim3(32, 8)>>>(w_qkv);
    transpose_w<1><<<dim3(32, 32), dim3(32, 8)>>>(w_proj);

    // 1) QKV GEMM (single fp16) -> Q (pre-scaled) / K / V, single fp16
    mma_gemm<1><<<dim3(3*DIM/128, BATCH*SEQ/128), 256, gemm_smem>>>(b_qkv, nullptr, 3*DIM);

    // 2) Flash attention (single fp16) -> single fp16 g_ah
    attn_mma<<<dim3(SEQ/128, BATCH*HEADS), 256, AT_SMEM>>>();

    // 3) Projection GEMM (single fp16)
    mma_gemm<2><<<dim3(DIM/128, BATCH*SEQ/128), 256, gemm_smem>>>(b_proj, out, DIM);
}